// round 1
// baseline (speedup 1.0000x reference)
#include <cuda_runtime.h>

// SpatialConv: 5-tap plus stencil, N=16, Ci=Co=256, H=W=64, fp32.
// out[n,o,h,w] = sum_c sum_k x_pad[n,c,h+dy_k,w+dx_k] * weight[o,c,k]
// taps (dy,dx): k0=(1,1) center, k1=(0,1) up, k2=(1,0) left, k3=(1,2) right, k4=(2,1) down
// (offsets applied to padded tensor with PAD=1, so effective offset = tap-1)

#define CI 256
#define CO 256
#define HH 64
#define WW 64
#define NBATCH 16
#define KTAPS 5
#define CT 16        // Ci chunk staged in smem
#define CO_TILE 64   // Co per block

__global__ __launch_bounds__(256, 2)
void spatial_conv_kernel(const float* __restrict__ x,
                         const float* __restrict__ wt,
                         float* __restrict__ out)
{
    __shared__ float xs[CT][3][WW + 2];          // 16*3*66*4 = 12672 B
    __shared__ float ws[CO_TILE][CT * KTAPS];    // 64*80*4   = 20480 B

    const int h   = blockIdx.y;
    const int n   = blockIdx.z;
    const int cob = blockIdx.x * CO_TILE;
    const int tid = threadIdx.x;
    const int tx  = tid & 15;   // pixel group: pixels tx*4 .. tx*4+3
    const int ty  = tid >> 4;   // co group:    co cob+ty*4 .. +3

    float acc[4][4];
#pragma unroll
    for (int i = 0; i < 4; i++)
#pragma unroll
        for (int j = 0; j < 4; j++) acc[i][j] = 0.f;

    for (int c0 = 0; c0 < CI; c0 += CT) {
        __syncthreads();
        // stage x halo: CT channels x 3 rows (h-1..h+1) x 66 cols (w-1..w+64)
        for (int e = tid; e < CT * 3 * (WW + 2); e += 256) {
            int c   = e / (3 * (WW + 2));
            int r   = (e / (WW + 2)) % 3;
            int col = e % (WW + 2);
            int gh  = h - 1 + r;
            int gw  = col - 1;
            float v = 0.f;
            if (gh >= 0 && gh < HH && gw >= 0 && gw < WW)
                v = x[(((size_t)n * CI + c0 + c) * HH + gh) * WW + gw];
            xs[c][r][col] = v;
        }
        // stage weights: CO_TILE x (CT*5), contiguous in (c,k) per o
        for (int e = tid; e < CO_TILE * CT * KTAPS; e += 256) {
            int o  = e / (CT * KTAPS);
            int ck = e % (CT * KTAPS);
            ws[o][ck] = wt[(size_t)(cob + o) * CI * KTAPS + c0 * KTAPS + ck];
        }
        __syncthreads();

#pragma unroll
        for (int c = 0; c < CT; c++) {
            float xm[4], xc[6], xp[4];
#pragma unroll
            for (int j = 0; j < 4; j++) xm[j] = xs[c][0][1 + tx * 4 + j];
#pragma unroll
            for (int j = 0; j < 6; j++) xc[j] = xs[c][1][tx * 4 + j];
#pragma unroll
            for (int j = 0; j < 4; j++) xp[j] = xs[c][2][1 + tx * 4 + j];
#pragma unroll
            for (int i = 0; i < 4; i++) {
                const float w_c = ws[ty * 4 + i][c * 5 + 0];
                const float w_u = ws[ty * 4 + i][c * 5 + 1];
                const float w_l = ws[ty * 4 + i][c * 5 + 2];
                const float w_r = ws[ty * 4 + i][c * 5 + 3];
                const float w_d = ws[ty * 4 + i][c * 5 + 4];
#pragma unroll
                for (int j = 0; j < 4; j++) {
                    acc[i][j] += w_c * xc[j + 1];
                    acc[i][j] += w_u * xm[j];
                    acc[i][j] += w_l * xc[j];
                    acc[i][j] += w_r * xc[j + 2];
                    acc[i][j] += w_d * xp[j];
                }
            }
        }
    }

#pragma unroll
    for (int i = 0; i < 4; i++) {
        float4 v = make_float4(acc[i][0], acc[i][1], acc[i][2], acc[i][3]);
        *(float4*)&out[(((size_t)n * CO + cob + ty * 4 + i) * HH + h) * WW + tx * 4] = v;
    }
}

extern "C" void kernel_launch(void* const* d_in, const int* in_sizes, int n_in,
                              void* d_out, int out_size)
{
    const float* x  = (const float*)d_in[0];
    const float* wt = (const float*)d_in[1];
    // d_in[2] = step (int), unused
    float* out = (float*)d_out;

    dim3 grid(CO / CO_TILE, HH, NBATCH);  // (4, 64, 16)
    spatial_conv_kernel<<<grid, 256>>>(x, wt, out);
}

// round 2
// speedup vs baseline: 2.0223x; 2.0223x over previous
#include <cuda_runtime.h>
#include <cstdint>

// SpatialConv as implicit GEMM on tensor cores (tf32 mma.sync).
// out[n,o,h,w] = sum_{c,k} x_shift_k[n,c,h,w] * W[o,c,k]
//   A = weight [Co, Ci*5] (row-major, contiguous in gmem)
//   B = im2col rows: kk=(c*5+tap) -> shifted pixel row of x
// taps (dy,dx): 0:(0,0) 1:(-1,0) 2:(0,-1) 3:(0,1) 4:(1,0)

#define CI 256
#define CO 256
#define HH 64
#define WW 64
#define NB 16
#define KT 5
#define KTOT (CI * KT)   // 1280
#define BM 128           // Co tile
#define BN 64            // pixel tile = one image row
#define CCH 8            // channels per K chunk
#define CK (CCH * KT)    // 40 K per chunk (5 k8-steps)
#define ASTRIDE 44       // 44 % 32 = 12 -> conflict-free A frag loads
#define BSTRIDE 72       // 72 % 32 = 8  -> conflict-free B frag loads

__device__ __forceinline__ uint32_t f2tf(float f) {
    uint32_t u;
    asm("cvt.rna.tf32.f32 %0, %1;" : "=r"(u) : "f"(f));
    return u;
}

__global__ __launch_bounds__(256, 2)
void conv_mma_kernel(const float* __restrict__ x,
                     const float* __restrict__ wt,
                     float* __restrict__ out)
{
    __shared__ uint32_t As[BM][ASTRIDE];   // 22528 B (40 cols used)
    __shared__ uint32_t Bs[CK][BSTRIDE];   // 11520 B (64 cols used)

    const int h    = blockIdx.y;
    const int n    = blockIdx.z;
    const int cob  = blockIdx.x * BM;
    const int tid  = threadIdx.x;
    const int lane = tid & 31;
    const int warp = tid >> 5;
    const int wm   = warp >> 1;   // 0..3 : warp M tile (32 rows)
    const int wn   = warp & 1;    // 0..1 : warp N tile (32 cols)
    const int gid  = lane >> 2;   // groupID 0..7
    const int tig  = lane & 3;    // thread-in-group 0..3

    float acc[2][4][4];
#pragma unroll
    for (int mi = 0; mi < 2; mi++)
#pragma unroll
        for (int ni = 0; ni < 4; ni++)
#pragma unroll
            for (int r = 0; r < 4; r++) acc[mi][ni][r] = 0.f;

    for (int ch = 0; ch < CI / CCH; ch++) {
        __syncthreads();

        // ---- stage A: weights [128 o][40 kk], kk contiguous in gmem ----
        for (int e = tid; e < BM * 10; e += 256) {
            int o = e / 10, q = e % 10;
            float4 v = *(const float4*)(wt + (size_t)(cob + o) * KTOT + ch * CK + q * 4);
            As[o][q * 4 + 0] = f2tf(v.x);
            As[o][q * 4 + 1] = f2tf(v.y);
            As[o][q * 4 + 2] = f2tf(v.z);
            As[o][q * 4 + 3] = f2tf(v.w);
        }
        // ---- stage B: 40 shifted rows x 64 pixels ----
        for (int e = tid; e < CK * WW; e += 256) {
            int kk  = e / WW, w = e % WW;
            int c   = ch * CCH + kk / KT;
            int tap = kk - (kk / KT) * KT;
            int dy  = (tap == 1) ? -1 : ((tap == 4) ? 1 : 0);
            int dx  = (tap == 2) ? -1 : ((tap == 3) ? 1 : 0);
            int gh  = h + dy, gw = w + dx;
            float v = 0.f;
            if ((unsigned)gh < HH && (unsigned)gw < WW)
                v = x[(((size_t)n * CI + c) * HH + gh) * WW + gw];
            Bs[kk][w] = f2tf(v);
        }
        __syncthreads();

        // ---- 5 k8-steps of m16n8k8 tf32 ----
#pragma unroll
        for (int kb = 0; kb < KT; kb++) {
            uint32_t a[2][4], b[4][2];
#pragma unroll
            for (int mi = 0; mi < 2; mi++) {
                int r = wm * 32 + mi * 16 + gid;
                a[mi][0] = As[r][kb * 8 + tig];
                a[mi][1] = As[r + 8][kb * 8 + tig];
                a[mi][2] = As[r][kb * 8 + tig + 4];
                a[mi][3] = As[r + 8][kb * 8 + tig + 4];
            }
#pragma unroll
            for (int ni = 0; ni < 4; ni++) {
                int cc = wn * 32 + ni * 8 + gid;
                b[ni][0] = Bs[kb * 8 + tig][cc];
                b[ni][1] = Bs[kb * 8 + tig + 4][cc];
            }
#pragma unroll
            for (int mi = 0; mi < 2; mi++)
#pragma unroll
                for (int ni = 0; ni < 4; ni++) {
                    asm volatile(
                        "mma.sync.aligned.m16n8k8.row.col.f32.tf32.tf32.f32 "
                        "{%0,%1,%2,%3}, {%4,%5,%6,%7}, {%8,%9}, {%0,%1,%2,%3};"
                        : "+f"(acc[mi][ni][0]), "+f"(acc[mi][ni][1]),
                          "+f"(acc[mi][ni][2]), "+f"(acc[mi][ni][3])
                        : "r"(a[mi][0]), "r"(a[mi][1]), "r"(a[mi][2]), "r"(a[mi][3]),
                          "r"(b[ni][0]), "r"(b[ni][1]));
                }
        }
    }

    // ---- epilogue: acc -> out[n, co, h, w] ----
#pragma unroll
    for (int mi = 0; mi < 2; mi++)
#pragma unroll
        for (int ni = 0; ni < 4; ni++) {
            int r0 = cob + wm * 32 + mi * 16 + gid;
            int c0 = wn * 32 + ni * 8 + tig * 2;
            float2 v0 = make_float2(acc[mi][ni][0], acc[mi][ni][1]);
            float2 v1 = make_float2(acc[mi][ni][2], acc[mi][ni][3]);
            *(float2*)&out[(((size_t)n * CO + r0) * HH + h) * WW + c0]     = v0;
            *(float2*)&out[(((size_t)n * CO + r0 + 8) * HH + h) * WW + c0] = v1;
        }
}

extern "C" void kernel_launch(void* const* d_in, const int* in_sizes, int n_in,
                              void* d_out, int out_size)
{
    const float* x  = (const float*)d_in[0];
    const float* wt = (const float*)d_in[1];
    float* out = (float*)d_out;

    dim3 grid(CO / BM, HH, NB);   // (2, 64, 16) = 2048 CTAs
    conv_mma_kernel<<<grid, 256>>>(x, wt, out);
}

// round 3
// speedup vs baseline: 4.5663x; 2.2580x over previous
#include <cuda_runtime.h>
#include <cstdint>

// SpatialConv implicit GEMM, tf32 mma.sync, cp.async double-buffered pipeline.
// K reordered: k8-step kb = tap kb over 8 channels (c = tig, tig+4).
// taps (dy,dx): k0:(0,0) k1:(-1,0) k2:(0,-1) k3:(0,1) k4:(1,0)

#define CI 256
#define CO 256
#define HH 64
#define WW 64
#define NB 16
#define KT 5
#define KTOT (CI*KT)     // 1280
#define BM 64            // Co tile
#define CCH 8            // channels per chunk
#define CK (CCH*KT)      // 40
#define NCH (CI/CCH)     // 32 chunks
#define AST 44           // A smem stride: (12*gid+5*tig)%32 all distinct
#define XST 72           // X smem stride: (24*tig+gid)%32 all distinct

__device__ __forceinline__ uint32_t f2tf(float f) {
    uint32_t u; asm("cvt.rna.tf32.f32 %0, %1;" : "=r"(u) : "f"(f)); return u;
}
__device__ __forceinline__ void cpa16(uint32_t dst, const void* src, int srcsz) {
    asm volatile("cp.async.cg.shared.global [%0], [%1], 16, %2;"
                 :: "r"(dst), "l"(src), "r"(srcsz));
}

__global__ __launch_bounds__(128, 5)
void conv_mma_kernel(const float* __restrict__ x,
                     const float* __restrict__ wt,
                     float* __restrict__ out)
{
    __shared__ float As[2][BM][AST];          // 22528 B
    __shared__ float Xs[2][CCH][3][XST];      // 13824 B  (data cols [4..68))

    const int h    = blockIdx.y;
    const int n    = blockIdx.z;
    const int cob  = blockIdx.x * BM;
    const int tid  = threadIdx.x;
    const int lane = tid & 31;
    const int warp = tid >> 5;
    const int wm   = warp >> 1;   // 0..1
    const int wn   = warp & 1;    // 0..1
    const int gid  = lane >> 2;
    const int tig  = lane & 3;

    const uint32_t sA = (uint32_t)__cvta_generic_to_shared(&As[0][0][0]);
    const uint32_t sX = (uint32_t)__cvta_generic_to_shared(&Xs[0][0][0][0]);

    // zero Xs border cols (0..3 and 68..71), both buffers; never overwritten
    for (int e = tid; e < 2 * CCH * 3 * 8; e += 128) {
        int b = e / (CCH * 3 * 8), rr = (e / 8) % (CCH * 3), q = e & 7;
        Xs[b][rr / 3][rr % 3][(q < 4) ? q : (64 + q)] = 0.f;
    }

    float acc[2][4][4];
#pragma unroll
    for (int mi = 0; mi < 2; mi++)
#pragma unroll
        for (int ni = 0; ni < 4; ni++)
#pragma unroll
            for (int r = 0; r < 4; r++) acc[mi][ni][r] = 0.f;

    // stage chunk ch into buffer buf
    auto stage = [&](int ch, int buf) {
        // A: weights [64 o][40 ck], gmem-contiguous, 640 x 16B -> 5/thread
#pragma unroll
        for (int i = 0; i < 5; i++) {
            int e = tid + i * 128;
            int o = e / 10, q = e % 10;
            uint32_t dst = sA + (uint32_t)(((buf * BM + o) * AST + q * 4) * 4);
            cpa16(dst, wt + (size_t)(cob + o) * KTOT + ch * CK + q * 4, 16);
        }
        // X: raw rows h-1..h+1 for 8 channels, 384 x 16B -> 3/thread
#pragma unroll
        for (int i = 0; i < 3; i++) {
            int e = tid + i * 128;
            int c = e / 48, r = (e / 16) % 3, q = e & 15;
            int gh = h - 1 + r;
            int ok = ((unsigned)gh < HH) ? 16 : 0;
            int ghc = ok ? gh : 0;
            uint32_t dst = sX + (uint32_t)(((((buf * CCH + c) * 3) + r) * XST + 4 + q * 4) * 4);
            cpa16(dst, x + (((size_t)n * CI + ch * CCH + c) * HH + ghc) * WW + q * 4, ok);
        }
    };

    stage(0, 0);
    asm volatile("cp.async.commit_group;");

    const int ROF[KT] = {1, 0, 1, 1, 2};
    const int DXF[KT] = {0, 0, -1, 1, 0};

    for (int ch = 0; ch < NCH; ch++) {
        const int buf = ch & 1;
        if (ch + 1 < NCH) stage(ch + 1, buf ^ 1);
        asm volatile("cp.async.commit_group;");
        asm volatile("cp.async.wait_group 1;");
        __syncthreads();

        const float (*A)[AST]     = As[buf];
        const float (*X)[3][XST]  = Xs[buf];

#pragma unroll
        for (int kb = 0; kb < KT; kb++) {
            uint32_t a[2][4], b[4][2];
#pragma unroll
            for (int mi = 0; mi < 2; mi++) {
                int r = wm * 32 + mi * 16 + gid;
                a[mi][0] = f2tf(A[r][tig * 5 + kb]);
                a[mi][1] = f2tf(A[r + 8][tig * 5 + kb]);
                a[mi][2] = f2tf(A[r][(tig + 4) * 5 + kb]);
                a[mi][3] = f2tf(A[r + 8][(tig + 4) * 5 + kb]);
            }
            const int rr = ROF[kb], dx = DXF[kb];
#pragma unroll
            for (int ni = 0; ni < 4; ni++) {
                int cc = wn * 32 + ni * 8 + gid + 4 + dx;
                b[ni][0] = f2tf(X[tig][rr][cc]);
                b[ni][1] = f2tf(X[tig + 4][rr][cc]);
            }
#pragma unroll
            for (int mi = 0; mi < 2; mi++)
#pragma unroll
                for (int ni = 0; ni < 4; ni++) {
                    asm volatile(
                        "mma.sync.aligned.m16n8k8.row.col.f32.tf32.tf32.f32 "
                        "{%0,%1,%2,%3}, {%4,%5,%6,%7}, {%8,%9}, {%0,%1,%2,%3};"
                        : "+f"(acc[mi][ni][0]), "+f"(acc[mi][ni][1]),
                          "+f"(acc[mi][ni][2]), "+f"(acc[mi][ni][3])
                        : "r"(a[mi][0]), "r"(a[mi][1]), "r"(a[mi][2]), "r"(a[mi][3]),
                          "r"(b[ni][0]), "r"(b[ni][1]));
                }
        }
        __syncthreads();
    }

    // epilogue
#pragma unroll
    for (int mi = 0; mi < 2; mi++)
#pragma unroll
        for (int ni = 0; ni < 4; ni++) {
            int r0 = cob + wm * 32 + mi * 16 + gid;
            int c0 = wn * 32 + ni * 8 + tig * 2;
            float2 v0 = make_float2(acc[mi][ni][0], acc[mi][ni][1]);
            float2 v1 = make_float2(acc[mi][ni][2], acc[mi][ni][3]);
            *(float2*)&out[(((size_t)n * CO + r0) * HH + h) * WW + c0]     = v0;
            *(float2*)&out[(((size_t)n * CO + r0 + 8) * HH + h) * WW + c0] = v1;
        }
}

extern "C" void kernel_launch(void* const* d_in, const int* in_sizes, int n_in,
                              void* d_out, int out_size)
{
    const float* x  = (const float*)d_in[0];
    const float* wt = (const float*)d_in[1];
    float* out = (float*)d_out;

    dim3 grid(CO / BM, HH, NB);   // (4, 64, 16) = 4096 CTAs
    conv_mma_kernel<<<grid, 128>>>(x, wt, out);
}